// round 11
// baseline (speedup 1.0000x reference)
#include <cuda_runtime.h>
#include <stdint.h>

#define Nn 2048
#define Ff 32
#define Ee 16
#define Kk 32

#define NT 256            // threads per block (8 warps)
#define NV (Nn * Ee / 4)  // 8192 float4 per edges row
#define CPW 40            // compacted slots per warp (avg nnz/warp ~12.8)
#define CAP (8 * CPW)     // 320 total slots

// Scratch (device globals — no allocation allowed)
__device__ float g_u[Nn * Ff];    // node_part + b_ne
__device__ float g_pre[Nn * Ff];  // (1+eps) * relu(nodes@W_n + b_n)

// Kernel A: per-node precompute. 65536 threads, one per (j,f).
__global__ void prep_kernel(const float* __restrict__ nodes,
                            const float* __restrict__ W_ne,
                            const float* __restrict__ b_ne,
                            const float* __restrict__ W_n,
                            const float* __restrict__ b_n,
                            const float* __restrict__ eps) {
    int t = blockIdx.x * blockDim.x + threadIdx.x;  // 0..N*F-1
    int j = t >> 5;
    int f = t & 31;
    const float* nrow = nodes + j * Ff;
    float s1 = 0.f, s2 = 0.f;
#pragma unroll
    for (int c = 0; c < Ff; c++) {
        float nv = nrow[c];
        s1 = fmaf(nv, W_ne[c * Ff + f], s1);
        s2 = fmaf(nv, W_n[c * Ff + f], s2);
    }
    g_u[t] = s1 + b_ne[f];
    g_pre[t] = (1.0f + eps[0]) * fmaxf(s2 + b_n[f], 0.f);
}

// One block per row i, 256 threads (8 warps), ~38 KB smem -> 4 CTAs/SM.
//  1. adj scan (ldcs) + adj->out copy (stcs) + per-warp ballot compaction;
//     warp w publishes its nonzero j's into FIXED slots [w*CPW, w*CPW+cnt)
//     of the j->slot map (no cross-warp prefix, one barrier saved).
//  2. streaming copy of edges row with ldcs/stcs (evict-first: the 512 MB
//     stream stays out of L2, keeping g_u and weights L2-hot); vectors whose
//     j is nonzero are also staged into a compacted 20 KB smem tile.
//  3. sparse msg from the compacted tile (LDS), g_u from L2-hot table;
//     8 warps x ~13 nnz, 4-way MLP unroll. cnt > CPW (pathological) falls
//     back to global reads -> correctness never depends on capacity.
//  4. block reduce + 32x32 FC + relu.
__global__ __launch_bounds__(NT, 4) void fused_kernel(
    const float* __restrict__ adj,
    const float* __restrict__ edges,
    const float* __restrict__ W_ne,
    const float* __restrict__ W_net,
    const float* __restrict__ b_net,
    float* __restrict__ out_adj,
    float* __restrict__ out_y,
    float* __restrict__ out_edges) {
    __shared__ float4 ctile[CAP * 4];  // 20480 B compacted edge vectors
    __shared__ uint16_t s_slot[Nn];    // 4096 B  j -> slot (0xFFFF = none)
    __shared__ uint16_t sjb[8 * 256];  // 4096 B  per-warp nonzero j lists
    __shared__ float sab[8 * 256];     // 8192 B  per-warp adj values
    __shared__ float smsg[8 * 32];     // partial messages

    int i = blockIdx.x;
    int t = threadIdx.x;
    int lane = t & 31;
    int w = t >> 5;  // 0..7

    const float* adjrow = adj + (size_t)i * Nn;
    float* oadj = out_adj + (size_t)i * Nn;
    const float4* erow4 =
        reinterpret_cast<const float4*>(edges + (size_t)i * Nn * Ee);
    float4* oe4 = reinterpret_cast<float4*>(out_edges + (size_t)i * Nn * Ee);

    // ---- Phase 0: init j->slot map ----
#pragma unroll
    for (int r = 0; r < Nn / NT; r++) s_slot[t + r * NT] = 0xFFFFu;

    // ---- Phase 1: adj scan + copy + compaction (fixed per-warp slots) ----
    // Warp w owns j in {w*32 + c*256 + lane : c in [0,8)} — same partition
    // and order as R3/R9/R10 -> identical summation order.
    uint16_t* sj = sjb + w * 256;
    float* sa = sab + w * 256;
    int cnt = 0;
#pragma unroll
    for (int c = 0; c < 8; c++) {
        int jb = w * 32 + c * NT;
        float a = __ldcs(&adjrow[jb + lane]);
        __stcs(&oadj[jb + lane], a);  // fused adj pass-through copy
        unsigned mask = __ballot_sync(0xffffffffu, a != 0.f);
        int pos = cnt + __popc(mask & ((1u << lane) - 1u));
        if (a != 0.f) {
            sj[pos] = (uint16_t)(jb + lane);
            sa[pos] = a;
        }
        cnt += __popc(mask);
    }
    __syncwarp();
    // Publish own slots (no cross-warp dependency).
    for (int idx = lane; idx < cnt && idx < CPW; idx += 32)
        s_slot[sj[idx]] = (uint16_t)(w * CPW + idx);
    __syncthreads();

    // ---- Phase 2: streaming copy (ldcs/stcs) + compacted staging ----
#pragma unroll 8
    for (int r = 0; r < NV / NT; r++) {
        int k = t + r * NT;
        float4 v = __ldcs(&erow4[k]);
        __stcs(&oe4[k], v);
        int slot = s_slot[k >> 2];
        if (slot != 0xFFFF) ctile[slot * 4 + (k & 3)] = v;
    }
    __syncthreads();

    // ---- Phase 3: sparse message from compacted tile, 4-way unrolled ----
    float we[Ee];
#pragma unroll
    for (int e = 0; e < Ee; e++) we[e] = W_ne[(Ff + e) * Ff + lane];

    float msg = 0.f;
    int idx = 0;
    if (cnt <= CPW) {
        // Fast path: all this warp's vectors are staged at w*CPW + idx.
        const float4* wtile = ctile + w * CPW * 4;
        for (; idx + 4 <= cnt; idx += 4) {
            int j0 = sj[idx], j1 = sj[idx + 1], j2 = sj[idx + 2],
                j3 = sj[idx + 3];
            float a0 = sa[idx], a1 = sa[idx + 1], a2 = sa[idx + 2],
                  a3 = sa[idx + 3];
            float u0 = g_u[j0 * Ff + lane];
            float u1 = g_u[j1 * Ff + lane];
            float u2 = g_u[j2 * Ff + lane];
            float u3 = g_u[j3 * Ff + lane];
            const float4* p0 = wtile + idx * 4;
            const float4* p1 = p0 + 4;
            const float4* p2 = p0 + 8;
            const float4* p3 = p0 + 12;
            float s0 = 0.f, s1 = 0.f, s2 = 0.f, s3 = 0.f;
#pragma unroll
            for (int q = 0; q < 4; q++) {
                float4 x = p0[q], y = p1[q], z = p2[q], v = p3[q];
                s0 = fmaf(x.x, we[4 * q + 0], s0);
                s0 = fmaf(x.y, we[4 * q + 1], s0);
                s0 = fmaf(x.z, we[4 * q + 2], s0);
                s0 = fmaf(x.w, we[4 * q + 3], s0);
                s1 = fmaf(y.x, we[4 * q + 0], s1);
                s1 = fmaf(y.y, we[4 * q + 1], s1);
                s1 = fmaf(y.z, we[4 * q + 2], s1);
                s1 = fmaf(y.w, we[4 * q + 3], s1);
                s2 = fmaf(z.x, we[4 * q + 0], s2);
                s2 = fmaf(z.y, we[4 * q + 1], s2);
                s2 = fmaf(z.z, we[4 * q + 2], s2);
                s2 = fmaf(z.w, we[4 * q + 3], s2);
                s3 = fmaf(v.x, we[4 * q + 0], s3);
                s3 = fmaf(v.y, we[4 * q + 1], s3);
                s3 = fmaf(v.z, we[4 * q + 2], s3);
                s3 = fmaf(v.w, we[4 * q + 3], s3);
            }
            msg = fmaf(a0, fmaxf(s0 + u0, 0.f), msg);
            msg = fmaf(a1, fmaxf(s1 + u1, 0.f), msg);
            msg = fmaf(a2, fmaxf(s2 + u2, 0.f), msg);
            msg = fmaf(a3, fmaxf(s3 + u3, 0.f), msg);
        }
    }
    // Tail + overflow fallback (idx >= CPW reads from global).
    for (; idx < cnt; idx++) {
        int j0 = sj[idx];
        float a0 = sa[idx];
        float u0 = g_u[j0 * Ff + lane];
        float4 x0, x1, x2, x3;
        if (idx < CPW) {
            const float4* p0 = ctile + (w * CPW + idx) * 4;
            x0 = p0[0]; x1 = p0[1]; x2 = p0[2]; x3 = p0[3];
        } else {
            const float4* p0 = erow4 + (size_t)j0 * 4;
            x0 = p0[0]; x1 = p0[1]; x2 = p0[2]; x3 = p0[3];
        }
        float s0 = 0.f;
        s0 = fmaf(x0.x, we[0], s0);
        s0 = fmaf(x0.y, we[1], s0);
        s0 = fmaf(x0.z, we[2], s0);
        s0 = fmaf(x0.w, we[3], s0);
        s0 = fmaf(x1.x, we[4], s0);
        s0 = fmaf(x1.y, we[5], s0);
        s0 = fmaf(x1.z, we[6], s0);
        s0 = fmaf(x1.w, we[7], s0);
        s0 = fmaf(x2.x, we[8], s0);
        s0 = fmaf(x2.y, we[9], s0);
        s0 = fmaf(x2.z, we[10], s0);
        s0 = fmaf(x2.w, we[11], s0);
        s0 = fmaf(x3.x, we[12], s0);
        s0 = fmaf(x3.y, we[13], s0);
        s0 = fmaf(x3.z, we[14], s0);
        s0 = fmaf(x3.w, we[15], s0);
        msg = fmaf(a0, fmaxf(s0 + u0, 0.f), msg);
    }

    smsg[w * 32 + lane] = msg;
    __syncthreads();

    // ---- Phase 4: epilogue (warp 0) ----
    if (w == 0) {
        float m = 0.f;
#pragma unroll
        for (int k = 0; k < 8; k++) m += smsg[k * 32 + lane];
        float p = g_pre[i * Ff + lane] + m;  // (1+eps)*node_term + msg
        float acc = b_net[lane];
#pragma unroll
        for (int f = 0; f < Ff; f++)
            acc = fmaf(__shfl_sync(0xffffffffu, p, f), W_net[f * Kk + lane],
                       acc);
        out_y[(size_t)i * Kk + lane] = fmaxf(acc, 0.f);
    }
}

extern "C" void kernel_launch(void* const* d_in, const int* in_sizes, int n_in,
                              void* d_out, int out_size) {
    const float* adj = (const float*)d_in[0];
    const float* nodes = (const float*)d_in[1];
    const float* edges = (const float*)d_in[2];
    const float* W_ne = (const float*)d_in[3];
    const float* b_ne = (const float*)d_in[4];
    const float* W_n = (const float*)d_in[5];
    const float* b_n = (const float*)d_in[6];
    const float* W_net = (const float*)d_in[7];
    const float* b_net = (const float*)d_in[8];
    const float* eps = (const float*)d_in[9];

    float* out = (float*)d_out;
    float* out_adj = out;                                       // [N,N]
    float* out_y = out + (size_t)Nn * Nn;                       // [N,K]
    float* out_edges = out + (size_t)Nn * Nn + (size_t)Nn * Kk; // [N,N,E]

    prep_kernel<<<(Nn * Ff) / 256, 256>>>(nodes, W_ne, b_ne, W_n, b_n, eps);
    fused_kernel<<<Nn, NT>>>(adj, edges, W_ne, W_net, b_net, out_adj, out_y,
                             out_edges);
}

// round 12
// speedup vs baseline: 1.3242x; 1.3242x over previous
#include <cuda_runtime.h>
#include <stdint.h>

#define Nn 2048
#define Ff 32
#define Ee 16
#define Kk 32

#define NT 256            // threads per block (8 warps)
#define NV (Nn * Ee / 4)  // 8192 float4 per edges row
#define CPW 40            // compacted slots per warp (avg nnz/warp ~12.8)
#define CAP (8 * CPW)     // 320 total slots

// Scratch (device globals — no allocation allowed)
__device__ float g_u[Nn * Ff];    // node_part + b_ne
__device__ float g_pre[Nn * Ff];  // (1+eps) * relu(nodes@W_n + b_n)

// Kernel A: per-node precompute. 65536 threads, one per (j,f).
__global__ void prep_kernel(const float* __restrict__ nodes,
                            const float* __restrict__ W_ne,
                            const float* __restrict__ b_ne,
                            const float* __restrict__ W_n,
                            const float* __restrict__ b_n,
                            const float* __restrict__ eps) {
    int t = blockIdx.x * blockDim.x + threadIdx.x;  // 0..N*F-1
    int j = t >> 5;
    int f = t & 31;
    const float* nrow = nodes + j * Ff;
    float s1 = 0.f, s2 = 0.f;
#pragma unroll
    for (int c = 0; c < Ff; c++) {
        float nv = nrow[c];
        s1 = fmaf(nv, W_ne[c * Ff + f], s1);
        s2 = fmaf(nv, W_n[c * Ff + f], s2);
    }
    g_u[t] = s1 + b_ne[f];
    g_pre[t] = (1.0f + eps[0]) * fmaxf(s2 + b_n[f], 0.f);
}

// One block per row i, 256 threads (8 warps), ~38 KB smem -> 4 CTAs/SM.
// R10 structure (plain loads/stores — cache hints regressed DRAM rate on
// sm_103a, R11) + fixed per-warp compaction slots (no cross-warp prefix).
//  1. adj scan + adj->out copy + per-warp ballot compaction into FIXED
//     slots [w*CPW, w*CPW+cnt) of the j->slot map.
//  2. streaming copy of edges row; vectors whose j is nonzero are also
//     staged into a compacted 20 KB smem tile (~5% of vectors).
//  3. sparse msg from the compacted tile (LDS broadcast), g_u from L2;
//     8 warps x ~13 nnz, 4-way MLP unroll. cnt > CPW falls back to global
//     reads -> correctness never depends on capacity.
//  4. block reduce + 32x32 FC + relu.
__global__ __launch_bounds__(NT, 4) void fused_kernel(
    const float* __restrict__ adj,
    const float* __restrict__ edges,
    const float* __restrict__ W_ne,
    const float* __restrict__ W_net,
    const float* __restrict__ b_net,
    float* __restrict__ out_adj,
    float* __restrict__ out_y,
    float* __restrict__ out_edges) {
    __shared__ float4 ctile[CAP * 4];  // 20480 B compacted edge vectors
    __shared__ uint16_t s_slot[Nn];    // 4096 B  j -> slot (0xFFFF = none)
    __shared__ uint16_t sjb[8 * 256];  // 4096 B  per-warp nonzero j lists
    __shared__ float sab[8 * 256];     // 8192 B  per-warp adj values
    __shared__ float smsg[8 * 32];     // partial messages

    int i = blockIdx.x;
    int t = threadIdx.x;
    int lane = t & 31;
    int w = t >> 5;  // 0..7

    const float* adjrow = adj + (size_t)i * Nn;
    float* oadj = out_adj + (size_t)i * Nn;
    const float4* erow4 =
        reinterpret_cast<const float4*>(edges + (size_t)i * Nn * Ee);
    float4* oe4 = reinterpret_cast<float4*>(out_edges + (size_t)i * Nn * Ee);

    // ---- Phase 0: init j->slot map ----
#pragma unroll
    for (int r = 0; r < Nn / NT; r++) s_slot[t + r * NT] = 0xFFFFu;

    // ---- Phase 1: adj scan + copy + compaction (fixed per-warp slots) ----
    // Warp w owns j in {w*32 + c*256 + lane : c in [0,8)} — same partition
    // and order as R3/R9/R10 -> identical summation order.
    uint16_t* sj = sjb + w * 256;
    float* sa = sab + w * 256;
    int cnt = 0;
#pragma unroll
    for (int c = 0; c < 8; c++) {
        int jb = w * 32 + c * NT;
        float a = adjrow[jb + lane];
        oadj[jb + lane] = a;  // fused adj pass-through copy
        unsigned mask = __ballot_sync(0xffffffffu, a != 0.f);
        int pos = cnt + __popc(mask & ((1u << lane) - 1u));
        if (a != 0.f) {
            sj[pos] = (uint16_t)(jb + lane);
            sa[pos] = a;
        }
        cnt += __popc(mask);
    }
    __syncwarp();
    // Publish own slots (no cross-warp dependency).
    for (int idx = lane; idx < cnt && idx < CPW; idx += 32)
        s_slot[sj[idx]] = (uint16_t)(w * CPW + idx);
    __syncthreads();

    // ---- Phase 2: streaming copy + conditional compacted staging ----
#pragma unroll 8
    for (int r = 0; r < NV / NT; r++) {
        int k = t + r * NT;
        float4 v = erow4[k];
        oe4[k] = v;
        int slot = s_slot[k >> 2];
        if (slot != 0xFFFF) ctile[slot * 4 + (k & 3)] = v;
    }
    __syncthreads();

    // ---- Phase 3: sparse message from compacted tile, 4-way unrolled ----
    float we[Ee];
#pragma unroll
    for (int e = 0; e < Ee; e++) we[e] = W_ne[(Ff + e) * Ff + lane];

    float msg = 0.f;
    int idx = 0;
    if (cnt <= CPW) {
        // Fast path: all this warp's vectors are staged at w*CPW + idx.
        const float4* wtile = ctile + w * CPW * 4;
        for (; idx + 4 <= cnt; idx += 4) {
            int j0 = sj[idx], j1 = sj[idx + 1], j2 = sj[idx + 2],
                j3 = sj[idx + 3];
            float a0 = sa[idx], a1 = sa[idx + 1], a2 = sa[idx + 2],
                  a3 = sa[idx + 3];
            float u0 = g_u[j0 * Ff + lane];
            float u1 = g_u[j1 * Ff + lane];
            float u2 = g_u[j2 * Ff + lane];
            float u3 = g_u[j3 * Ff + lane];
            const float4* p0 = wtile + idx * 4;
            const float4* p1 = p0 + 4;
            const float4* p2 = p0 + 8;
            const float4* p3 = p0 + 12;
            float s0 = 0.f, s1 = 0.f, s2 = 0.f, s3 = 0.f;
#pragma unroll
            for (int q = 0; q < 4; q++) {
                float4 x = p0[q], y = p1[q], z = p2[q], v = p3[q];
                s0 = fmaf(x.x, we[4 * q + 0], s0);
                s0 = fmaf(x.y, we[4 * q + 1], s0);
                s0 = fmaf(x.z, we[4 * q + 2], s0);
                s0 = fmaf(x.w, we[4 * q + 3], s0);
                s1 = fmaf(y.x, we[4 * q + 0], s1);
                s1 = fmaf(y.y, we[4 * q + 1], s1);
                s1 = fmaf(y.z, we[4 * q + 2], s1);
                s1 = fmaf(y.w, we[4 * q + 3], s1);
                s2 = fmaf(z.x, we[4 * q + 0], s2);
                s2 = fmaf(z.y, we[4 * q + 1], s2);
                s2 = fmaf(z.z, we[4 * q + 2], s2);
                s2 = fmaf(z.w, we[4 * q + 3], s2);
                s3 = fmaf(v.x, we[4 * q + 0], s3);
                s3 = fmaf(v.y, we[4 * q + 1], s3);
                s3 = fmaf(v.z, we[4 * q + 2], s3);
                s3 = fmaf(v.w, we[4 * q + 3], s3);
            }
            msg = fmaf(a0, fmaxf(s0 + u0, 0.f), msg);
            msg = fmaf(a1, fmaxf(s1 + u1, 0.f), msg);
            msg = fmaf(a2, fmaxf(s2 + u2, 0.f), msg);
            msg = fmaf(a3, fmaxf(s3 + u3, 0.f), msg);
        }
    }
    // Tail + overflow fallback (idx >= CPW reads from global).
    for (; idx < cnt; idx++) {
        int j0 = sj[idx];
        float a0 = sa[idx];
        float u0 = g_u[j0 * Ff + lane];
        float4 x0, x1, x2, x3;
        if (idx < CPW) {
            const float4* p0 = ctile + (w * CPW + idx) * 4;
            x0 = p0[0]; x1 = p0[1]; x2 = p0[2]; x3 = p0[3];
        } else {
            const float4* p0 = erow4 + (size_t)j0 * 4;
            x0 = p0[0]; x1 = p0[1]; x2 = p0[2]; x3 = p0[3];
        }
        float s0 = 0.f;
        s0 = fmaf(x0.x, we[0], s0);
        s0 = fmaf(x0.y, we[1], s0);
        s0 = fmaf(x0.z, we[2], s0);
        s0 = fmaf(x0.w, we[3], s0);
        s0 = fmaf(x1.x, we[4], s0);
        s0 = fmaf(x1.y, we[5], s0);
        s0 = fmaf(x1.z, we[6], s0);
        s0 = fmaf(x1.w, we[7], s0);
        s0 = fmaf(x2.x, we[8], s0);
        s0 = fmaf(x2.y, we[9], s0);
        s0 = fmaf(x2.z, we[10], s0);
        s0 = fmaf(x2.w, we[11], s0);
        s0 = fmaf(x3.x, we[12], s0);
        s0 = fmaf(x3.y, we[13], s0);
        s0 = fmaf(x3.z, we[14], s0);
        s0 = fmaf(x3.w, we[15], s0);
        msg = fmaf(a0, fmaxf(s0 + u0, 0.f), msg);
    }

    smsg[w * 32 + lane] = msg;
    __syncthreads();

    // ---- Phase 4: epilogue (warp 0) ----
    if (w == 0) {
        float m = 0.f;
#pragma unroll
        for (int k = 0; k < 8; k++) m += smsg[k * 32 + lane];
        float p = g_pre[i * Ff + lane] + m;  // (1+eps)*node_term + msg
        float acc = b_net[lane];
#pragma unroll
        for (int f = 0; f < Ff; f++)
            acc = fmaf(__shfl_sync(0xffffffffu, p, f), W_net[f * Kk + lane],
                       acc);
        out_y[(size_t)i * Kk + lane] = fmaxf(acc, 0.f);
    }
}

extern "C" void kernel_launch(void* const* d_in, const int* in_sizes, int n_in,
                              void* d_out, int out_size) {
    const float* adj = (const float*)d_in[0];
    const float* nodes = (const float*)d_in[1];
    const float* edges = (const float*)d_in[2];
    const float* W_ne = (const float*)d_in[3];
    const float* b_ne = (const float*)d_in[4];
    const float* W_n = (const float*)d_in[5];
    const float* b_n = (const float*)d_in[6];
    const float* W_net = (const float*)d_in[7];
    const float* b_net = (const float*)d_in[8];
    const float* eps = (const float*)d_in[9];

    float* out = (float*)d_out;
    float* out_adj = out;                                       // [N,N]
    float* out_y = out + (size_t)Nn * Nn;                       // [N,K]
    float* out_edges = out + (size_t)Nn * Nn + (size_t)Nn * Kk; // [N,N,E]

    prep_kernel<<<(Nn * Ff) / 256, 256>>>(nodes, W_ne, b_ne, W_n, b_n, eps);
    fused_kernel<<<Nn, NT>>>(adj, edges, W_ne, W_net, b_net, out_adj, out_y,
                             out_edges);
}